// round 14
// baseline (speedup 1.0000x reference)
#include <cuda_runtime.h>
#include <math.h>
#include <stdint.h>

#define Bsz  64
#define Tlen 2048
#define Hd   128
#define G4   512
#define Cout 7
#define RST  68                     // ring floats per k-row (4-aligned, low-conflict)
#define SLOTF (Hd * RST)            // 8704 floats per ring slot

// ---------------- device scratch ----------------
__device__ float g_v0[G4];
__device__ float g_u0[G4];
__device__ float g_pool[Bsz * 3 * Hd];

__device__ __forceinline__ float sigf(float x)  { return 1.0f / (1.0f + __expf(-x)); }
__device__ __forceinline__ float tanhfast(float x) {
    return fmaf(-2.0f, 1.0f / (__expf(2.0f * x) + 1.0f), 1.0f);
}

// ---- packed f32x2 (Blackwell FFMA2) ----
__device__ __forceinline__ void fma2(unsigned long long& d, unsigned long long a, unsigned long long b) {
    asm("fma.rn.f32x2 %0, %1, %2, %0;" : "+l"(d) : "l"(a), "l"(b));
}
__device__ __forceinline__ float2 upk2(unsigned long long v) {
    float2 r; asm("mov.b64 {%0, %1}, %2;" : "=f"(r.x), "=f"(r.y) : "l"(v)); return r;
}
__device__ __forceinline__ unsigned long long splat2(float f) {
    unsigned long long v; asm("mov.b64 %0, {%1, %1};" : "=l"(v) : "f"(f)); return v;
}

__device__ __forceinline__ uint32_t smem_u32(const void* p) {
    uint32_t a;
    asm("{ .reg .u64 t; cvta.to.shared.u64 t, %1; cvt.u32.u64 %0, t; }" : "=r"(a) : "l"(p));
    return a;
}
__device__ __forceinline__ uint32_t mapa32(uint32_t a, uint32_t rank) {
    uint32_t d;
    asm("mapa.shared::cluster.u32 %0, %1, %2;" : "=r"(d) : "r"(a), "r"(rank));
    return d;
}
__device__ __forceinline__ void st_async_remote(uint32_t raddr, float v, uint32_t rmbar) {
    asm volatile("st.async.shared::cluster.mbarrier::complete_tx::bytes.b32 [%0], %1, [%2];"
                 :: "r"(raddr), "r"(__float_as_uint(v)), "r"(rmbar) : "memory");
}
__device__ __forceinline__ void mbar_init(uint32_t mbar, uint32_t cnt) {
    asm volatile("mbarrier.init.shared.b64 [%0], %1;" :: "r"(mbar), "r"(cnt) : "memory");
}
__device__ __forceinline__ void mbar_expect_tx(uint32_t mbar, uint32_t bytes) {
    asm volatile("mbarrier.arrive.expect_tx.shared.b64 _, [%0], %1;" :: "r"(mbar), "r"(bytes) : "memory");
}
__device__ __forceinline__ void mbar_wait(uint32_t mbar, uint32_t parity) {
    uint32_t done;
    asm volatile(
        "{\n\t.reg .pred p;\n\t"
        "mbarrier.try_wait.parity.acquire.cluster.shared::cta.b64 p, [%1], %2;\n\t"
        "selp.b32 %0, 1, 0, p;\n\t}"
        : "=r"(done) : "r"(mbar), "r"(parity) : "memory");
    if (!done) {
        asm volatile(
            "{\n\t.reg .pred P1;\n\t"
            "WL_%=:\n\t"
            "mbarrier.try_wait.parity.acquire.cluster.shared::cta.b64 P1, [%0], %1, 0x989680;\n\t"
            "@P1 bra.uni WD_%=;\n\t"
            "bra.uni WL_%=;\n\t"
            "WD_%=:\n\t}"
            :: "r"(mbar), "r"(parity) : "memory");
    }
}
__device__ __forceinline__ void bar_grp(int id) {
    asm volatile("bar.sync %0, 256;" :: "r"(id) : "memory");
}

// ---------------- prep ----------------
__global__ void prep_kernel(const float* __restrict__ Wih0, const float* __restrict__ ffw,
                            const float* __restrict__ ffb,  const float* __restrict__ b0) {
    int g = blockIdx.x * 64 + threadIdx.x;
    float v = 0.f, u = 0.f;
    #pragma unroll 8
    for (int k = 0; k < Hd; k++) {
        float w = Wih0[g * Hd + k];
        v = fmaf(w, ffw[k], v);
        u = fmaf(w, ffb[k], u);
    }
    g_v0[g] = v;
    g_u0[g] = u + b0[g];
}

// ---------------- fused 2-layer pipelined LSTM ----------------
// 64 clusters of 2 CTAs, 512 threads each. Warps 0-7 (group A) = layer-0
// recurrence; warps 8-15 (group B) = layer-1 recurrence + input GEMV from smem.
// A stages h(t) into a 2-slot [k][t] ring; 64-step chunk flags (fence+volatile).
// Each group has its own DSMEM h-exchange (h-split across cluster ranks) and
// its own named barrier. No global H1/G1, no GEMM kernel.
__global__ __launch_bounds__(512, 1) __cluster_dims__(2, 1, 1)
void fused_lstm(const float* __restrict__ Whh0, const float* __restrict__ Whh1,
                const float* __restrict__ Wih1, const float* __restrict__ b1,
                const float* __restrict__ xin,  const int* __restrict__ lengths) {
    __shared__ __align__(16) float h_sA[2][Hd];
    __shared__ __align__(16) float h_sB[2][Hd];
    __shared__ float actA[256];
    __shared__ float actB[256];
    __shared__ __align__(8) unsigned long long mbar[4];
    __shared__ int s_doneA, s_doneB;
    extern __shared__ __align__(16) float dynsm[];
    float* Wsm  = dynsm;                 // [k][nc] 128*256 f32 = 128 KB
    float* ring = Wsm + 128 * 256;       // 2 slots * 128 k * RST
    float* xrow = ring + 2 * SLOTF;      // 2048 f32

    const int tid  = threadIdx.x;
    const int grp  = tid >> 8;           // 0 = A (layer0), 1 = B (layer1)
    const int ltid = tid & 255;
    const int rank = blockIdx.x & 1;
    const int b    = blockIdx.x >> 1;
    const int type = ltid >> 6;
    const int hloc = ltid & 63;
    const int h_idx = 64 * rank + hloc;
    const int g    = type * 128 + h_idx;
    const int kloc = 64 * rank;
    const int krem = 64 * (1 - rank);

    // ---- recurrent weights (own layer) ----
    const float* Whh = grp ? Whh1 : Whh0;
    ulonglong2 w2[32];
    #pragma unroll
    for (int q = 0; q < 16; q++)
        w2[q] = *(const ulonglong2*)(Whh + (size_t)g * Hd + kloc + 4 * q);
    #pragma unroll
    for (int q = 0; q < 16; q++)
        w2[16 + q] = *(const ulonglong2*)(Whh + (size_t)g * Hd + krem + 4 * q);

    // ---- mbarriers: [0],[1] = group A parities; [2],[3] = group B ----
    if (tid == 0) {
        s_doneA = 0; s_doneB = 0;
        #pragma unroll
        for (int i = 0; i < 4; i++) {
            mbar_init(smem_u32(&mbar[i]), 1);
            mbar_expect_tx(smem_u32(&mbar[i]), 256);
        }
    }
    const uint32_t peer = rank ^ 1;
    float* h_own = grp ? &h_sB[0][0] : &h_sA[0][0];
    const uint32_t mbL0 = smem_u32(&mbar[2 * grp]);
    const uint32_t mbL1 = smem_u32(&mbar[2 * grp + 1]);
    const uint32_t r_h0  = mapa32(smem_u32(h_own + h_idx), peer);
    const uint32_t r_h1  = mapa32(smem_u32(h_own + Hd + h_idx), peer);
    const uint32_t r_mb0 = mapa32(mbL0, peer);
    const uint32_t r_mb1 = mapa32(mbL1, peer);

    // ---- init data ----
    float vg = 0.f, ug = 0.f, bias = 0.f;
    if (grp == 0) {
        vg = g_v0[g]; ug = g_u0[g];
        for (int i = ltid; i < Tlen; i += 256) xrow[i] = xin[(size_t)b * Tlen + i];
    } else {
        bias = b1[g];
    }
    // Wsm[k][nc] = Wih1[g(nc)][k], filled by all 512 threads
    for (int idx = tid; idx < 128 * 256; idx += 512) {
        int k = idx >> 8, nc = idx & 255;
        int gg = (nc >> 6) * 128 + 64 * rank + (nc & 63);
        Wsm[k * 256 + nc] = Wih1[(size_t)gg * Hd + k];
    }
    if (ltid < Hd) h_own[ltid] = 0.f;    // slot 0 of own group's h buffer
    __syncthreads();
    asm volatile("barrier.cluster.arrive.aligned;" ::: "memory");
    asm volatile("barrier.cluster.wait.aligned;" ::: "memory");

    float cst = 0.f;
    uint32_t ph0 = 0, ph1 = 0;

    if (grp == 0) {
        // ==================== group A: layer-0 ====================
        float* hs = &h_sA[0][0];
        for (int t = 0; t < Tlen; t++) {
            const int p = t & 1, pn = p ^ 1;
            if ((t & 63) == 1) {                      // ring-slot backpressure
                int need = (t >> 6) - 1;
                while (*(volatile int*)&s_doneB < need) __nanosleep(64);
            }
            float a_in = fmaf(xrow[t], vg, ug);

            const ulonglong2* hp = (const ulonglong2*)(hs + p * Hd);
            const ulonglong2* hL = hp + (kloc >> 2);
            const ulonglong2* hR = hp + (krem >> 2);

            unsigned long long acc0 = 0ULL, acc1 = 0ULL;
            #pragma unroll
            for (int q = 0; q < 16; q++) {
                ulonglong2 hv = hL[q];
                fma2(acc0, hv.x, w2[q].x);
                fma2(acc1, hv.y, w2[q].y);
            }
            if (t > 0) {
                if (p == 0) { mbar_wait(mbL0, ph0); ph0 ^= 1; }
                else        { mbar_wait(mbL1, ph1); ph1 ^= 1; }
                if (ltid == 0) mbar_expect_tx(p ? mbL1 : mbL0, 256);
                // h(t-1) complete in hs[p]: stage ring row t-1
                if (ltid < Hd) {
                    int r = (t - 1) & 63, slot = ((t - 1) >> 6) & 1;
                    ring[slot * SLOTF + ltid * RST + r] = hs[p * Hd + ltid];
                }
            }
            #pragma unroll
            for (int q = 0; q < 16; q++) {
                ulonglong2 hv = hR[q];
                fma2(acc0, hv.x, w2[16 + q].x);
                fma2(acc1, hv.y, w2[16 + q].y);
            }
            float2 u0 = upk2(acc0), u1 = upk2(acc1);
            float A = a_in + ((u0.x + u0.y) + (u1.x + u1.y));
            float av = (type == 2) ? tanhfast(A) : sigf(A);
            actA[ltid] = av;
            bar_grp(1);
            if ((t & 63) == 0 && t > 0 && ltid == 0) {       // chunk t/64-1 staged
                __threadfence_block();
                *(volatile int*)&s_doneA = t >> 6;
            }
            if (ltid < 64) {
                float iv = actA[ltid],       fv = actA[64 + ltid];
                float gv = actA[128 + ltid], ov = actA[192 + ltid];
                cst = fmaf(fv, cst, iv * gv);
                float h = ov * tanhfast(cst);
                st_async_remote(pn ? r_h1 : r_h0, h, pn ? r_mb1 : r_mb0);
                hs[pn * Hd + h_idx] = h;
            }
            bar_grp(1);
        }
        // tail: stage row 2047 (arrives on parity-0 barrier), publish chunk 32
        mbar_wait(mbL0, ph0);
        if (ltid < Hd) ring[1 * SLOTF + ltid * RST + 63] = hs[0 * Hd + ltid];
        bar_grp(1);
        if (ltid == 0) {
            __threadfence_block();
            *(volatile int*)&s_doneA = 32;
        }
    } else {
        // ==================== group B: layer-1 + GEMV ====================
        float* hs = &h_sB[0][0];
        float sum = 0.f, mx = -INFINITY, last = 0.f;
        const int len = lengths[b];

        for (int cc = 0; cc < Tlen / 64; cc++) {
            while (*(volatile int*)&s_doneA < cc + 1) __nanosleep(64);
            __threadfence_block();
            const float* rs = ring + (cc & 1) * SLOTF;

            for (int blk = 0; blk < 8; blk++) {
                // ---- gemv for 8 timesteps: z(t) = Wih1[g,:] . h1(t) ----
                unsigned long long z4[4] = {0ULL, 0ULL, 0ULL, 0ULL};
                const float* rb = rs + blk * 8;
                #pragma unroll 4
                for (int k = 0; k < 128; k++) {
                    unsigned long long ws = splat2(Wsm[k * 256 + ltid]);
                    ulonglong2 hA = *(const ulonglong2*)(rb + k * RST);       // t+0..3
                    ulonglong2 hB = *(const ulonglong2*)(rb + k * RST + 4);   // t+4..7
                    fma2(z4[0], ws, hA.x);
                    fma2(z4[1], ws, hA.y);
                    fma2(z4[2], ws, hB.x);
                    fma2(z4[3], ws, hB.y);
                }
                // ---- 8 recurrence steps consuming z ----
                for (int s = 0; s < 8; s++) {
                    const int t = cc * 64 + blk * 8 + s;
                    const int p = t & 1, pn = p ^ 1;
                    float2 zz = upk2(z4[s >> 1]);
                    float a_in = ((s & 1) ? zz.y : zz.x) + bias;

                    const ulonglong2* hp = (const ulonglong2*)(hs + p * Hd);
                    const ulonglong2* hL = hp + (kloc >> 2);
                    const ulonglong2* hR = hp + (krem >> 2);

                    unsigned long long acc0 = 0ULL, acc1 = 0ULL;
                    #pragma unroll
                    for (int q = 0; q < 16; q++) {
                        ulonglong2 hv = hL[q];
                        fma2(acc0, hv.x, w2[q].x);
                        fma2(acc1, hv.y, w2[q].y);
                    }
                    if (t > 0) {
                        if (p == 0) { mbar_wait(mbL0, ph0); ph0 ^= 1; }
                        else        { mbar_wait(mbL1, ph1); ph1 ^= 1; }
                        if (ltid == 0) mbar_expect_tx(p ? mbL1 : mbL0, 256);
                    }
                    #pragma unroll
                    for (int q = 0; q < 16; q++) {
                        ulonglong2 hv = hR[q];
                        fma2(acc0, hv.x, w2[16 + q].x);
                        fma2(acc1, hv.y, w2[16 + q].y);
                    }
                    float2 u0 = upk2(acc0), u1 = upk2(acc1);
                    float A = a_in + ((u0.x + u0.y) + (u1.x + u1.y));
                    float av = (type == 2) ? tanhfast(A) : sigf(A);
                    actB[ltid] = av;
                    bar_grp(2);
                    if (ltid < 64) {
                        float iv = actB[ltid],       fv = actB[64 + ltid];
                        float gv = actB[128 + ltid], ov = actB[192 + ltid];
                        cst = fmaf(fv, cst, iv * gv);
                        float h = ov * tanhfast(cst);
                        st_async_remote(pn ? r_h1 : r_h0, h, pn ? r_mb1 : r_mb0);
                        hs[pn * Hd + h_idx] = h;
                        if (t < len) { sum += h; mx = fmaxf(mx, h); }
                        if (t == len - 1) last = h;
                    }
                    bar_grp(2);
                }
            }
            if (ltid == 0) {
                __threadfence_block();
                *(volatile int*)&s_doneB = cc + 1;
            }
        }
        if (ltid < 64) {
            g_pool[b * 384 + h_idx]          = sum / (float)len;
            g_pool[b * 384 + Hd + h_idx]     = mx;
            g_pool[b * 384 + 2 * Hd + h_idx] = last;
        }
    }

    asm volatile("barrier.cluster.arrive.aligned;" ::: "memory");
    asm volatile("barrier.cluster.wait.aligned;" ::: "memory");
}

// ---------------- final linear: 64 CTAs, warp w -> class w ----------------
__global__ __launch_bounds__(256)
void final_kernel(const float* __restrict__ lw, const float* __restrict__ lb,
                  float* __restrict__ out) {
    const int b = blockIdx.x;
    const int wid = threadIdx.x >> 5;
    const int lane = threadIdx.x & 31;
    if (wid >= Cout) return;
    float s = 0.f;
    const float* p = g_pool + b * 384;
    const float* wv = lw + wid * 384;
    #pragma unroll
    for (int j = lane; j < 384; j += 32) s = fmaf(p[j], wv[j], s);
    #pragma unroll
    for (int o = 16; o > 0; o >>= 1) s += __shfl_xor_sync(0xffffffff, s, o);
    if (lane == 0) out[b * Cout + wid] = s + lb[wid];
}

// ---------------- launch ----------------
extern "C" void kernel_launch(void* const* d_in, const int* in_sizes, int n_in,
                              void* d_out, int out_size) {
    const float* x    = (const float*)d_in[0];
    const int*   lens = (const int*)  d_in[1];
    const float* ffw  = (const float*)d_in[2];
    const float* ffb  = (const float*)d_in[3];
    const float* Wih0 = (const float*)d_in[4];
    const float* Whh0 = (const float*)d_in[5];
    const float* b0   = (const float*)d_in[6];
    const float* Wih1 = (const float*)d_in[7];
    const float* Whh1 = (const float*)d_in[8];
    const float* b1   = (const float*)d_in[9];
    const float* lw   = (const float*)d_in[10];
    const float* lb   = (const float*)d_in[11];
    float* out = (float*)d_out;

    // dynamic smem: Wih1 slice 128 KB + 2-slot ring + xrow
    const int DYN = (128 * 256 + 2 * SLOTF + Tlen) * (int)sizeof(float);   // ~207 KB
    cudaFuncSetAttribute(fused_lstm, cudaFuncAttributeMaxDynamicSharedMemorySize, DYN);

    prep_kernel<<<8, 64>>>(Wih0, ffw, ffb, b0);
    fused_lstm<<<2 * Bsz, 512, DYN>>>(Whh0, Whh1, Wih1, b1, x, lens);
    final_kernel<<<Bsz, 256>>>(lw, lb, out);
}

// round 16
// speedup vs baseline: 2.0660x; 2.0660x over previous
#include <cuda_runtime.h>
#include <math.h>
#include <stdint.h>

#define Bsz  64
#define Tlen 2048
#define Hd   128
#define G4   512
#define Cout 7

// ---------------- device scratch ----------------
__device__ float g_v0[G4];
__device__ float g_u0[G4];
__device__ float g_H1[(size_t)Tlen * Bsz * Hd];     // layer-0 h stream [t][b][h]
__device__ float g_G1[(size_t)Tlen * Bsz * G4];     // layer-1 input-gate preacts [t][b][g]
__device__ float g_pool[Bsz * 3 * Hd];

__device__ __forceinline__ float sigf(float x)  { return 1.0f / (1.0f + __expf(-x)); }
__device__ __forceinline__ float tanhfast(float x) {
    return fmaf(-2.0f, 1.0f / (__expf(2.0f * x) + 1.0f), 1.0f);
}

// ---- packed f32x2 (Blackwell FFMA2) ----
__device__ __forceinline__ void fma2(unsigned long long& d, unsigned long long a, unsigned long long b) {
    asm("fma.rn.f32x2 %0, %1, %2, %0;" : "+l"(d) : "l"(a), "l"(b));
}
__device__ __forceinline__ float2 upk2(unsigned long long v) {
    float2 r; asm("mov.b64 {%0, %1}, %2;" : "=f"(r.x), "=f"(r.y) : "l"(v)); return r;
}

// ---- tf32 ----
__device__ __forceinline__ uint32_t f2tf(float f) {
    uint32_t r; asm("cvt.rna.tf32.f32 %0, %1;" : "=r"(r) : "f"(f)); return r;
}
__device__ __forceinline__ void mma_tf32(float* c, const uint32_t* a, const uint32_t* b) {
    asm("mma.sync.aligned.m16n8k8.row.col.f32.tf32.tf32.f32 "
        "{%0,%1,%2,%3}, {%4,%5,%6,%7}, {%8,%9}, {%0,%1,%2,%3};"
        : "+f"(c[0]), "+f"(c[1]), "+f"(c[2]), "+f"(c[3])
        : "r"(a[0]), "r"(a[1]), "r"(a[2]), "r"(a[3]), "r"(b[0]), "r"(b[1]));
}

__device__ __forceinline__ uint32_t smem_u32(const void* p) {
    uint32_t a;
    asm("{ .reg .u64 t; cvta.to.shared.u64 t, %1; cvt.u32.u64 %0, t; }" : "=r"(a) : "l"(p));
    return a;
}
__device__ __forceinline__ uint32_t mapa32(uint32_t a, uint32_t rank) {
    uint32_t d;
    asm("mapa.shared::cluster.u32 %0, %1, %2;" : "=r"(d) : "r"(a), "r"(rank));
    return d;
}
__device__ __forceinline__ void st_async_remote(uint32_t raddr, float v, uint32_t rmbar) {
    asm volatile("st.async.shared::cluster.mbarrier::complete_tx::bytes.b32 [%0], %1, [%2];"
                 :: "r"(raddr), "r"(__float_as_uint(v)), "r"(rmbar) : "memory");
}
__device__ __forceinline__ void mbar_init(uint32_t mbar, uint32_t cnt) {
    asm volatile("mbarrier.init.shared.b64 [%0], %1;" :: "r"(mbar), "r"(cnt) : "memory");
}
__device__ __forceinline__ void mbar_expect_tx(uint32_t mbar, uint32_t bytes) {
    asm volatile("mbarrier.arrive.expect_tx.shared.b64 _, [%0], %1;" :: "r"(mbar), "r"(bytes) : "memory");
}
__device__ __forceinline__ void mbar_wait(uint32_t mbar, uint32_t parity) {
    uint32_t done;
    asm volatile(
        "{\n\t.reg .pred p;\n\t"
        "mbarrier.try_wait.parity.acquire.cluster.shared::cta.b64 p, [%1], %2;\n\t"
        "selp.b32 %0, 1, 0, p;\n\t}"
        : "=r"(done) : "r"(mbar), "r"(parity) : "memory");
    if (!done) {
        asm volatile(
            "{\n\t.reg .pred P1;\n\t"
            "WL_%=:\n\t"
            "mbarrier.try_wait.parity.acquire.cluster.shared::cta.b64 P1, [%0], %1, 0x989680;\n\t"
            "@P1 bra.uni WD_%=;\n\t"
            "bra.uni WL_%=;\n\t"
            "WD_%=:\n\t}"
            :: "r"(mbar), "r"(parity) : "memory");
    }
}

// ---------------- prep ----------------
__global__ void prep_kernel(const float* __restrict__ Wih0, const float* __restrict__ ffw,
                            const float* __restrict__ ffb,  const float* __restrict__ b0) {
    int g = blockIdx.x * 64 + threadIdx.x;
    float v = 0.f, u = 0.f;
    #pragma unroll 8
    for (int k = 0; k < Hd; k++) {
        float w = Wih0[g * Hd + k];
        v = fmaf(w, ffw[k], v);
        u = fmaf(w, ffb[k], u);
    }
    g_v0[g] = v;
    g_u0[g] = u + b0[g];
}

// ---------------- h-split cluster LSTM, k-pair threads (fixed indices) ----------------
// 64 clusters of 2 CTAs, 512 threads. Thread pair (2*gi, 2*gi+1) shares gate gi;
// each lane handles 32 local-k + 32 remote-k weights (32 regs); halves combine
// via shfl_xor(1). h-update path uses uidx = 64*rank + (tid&63)  [R15 bug fix].
template <int LAYER>
__global__ __launch_bounds__(512, 1) __cluster_dims__(2, 1, 1)
void lstm_kernel(const float* __restrict__ Whh,
                 const float* __restrict__ xin,
                 const int*   __restrict__ lengths) {
    __shared__ __align__(16) float h_s[2][Hd];
    __shared__ float act_s[256];
    __shared__ float xrow[Tlen];
    __shared__ __align__(8) unsigned long long mbar[2];

    const int tid  = threadIdx.x;        // 0..511
    const int gi   = tid >> 1;           // gate index within CTA (0..255)
    const int kh   = tid & 1;            // k-half of the pair
    const int rank = blockIdx.x & 1;
    const int b    = blockIdx.x >> 1;
    const int type = gi >> 6;            // 0=i 1=f 2=g 3=o (128-thread blocks)
    const int hloc = gi & 63;
    const int h_idx = 64 * rank + hloc;  // gate-path h index
    const int g    = type * 128 + h_idx;
    const int kloc = 64 * rank + 32 * kh;
    const int krem = 64 * (1 - rank) + 32 * kh;
    const int uidx = 64 * rank + (tid & 63);   // h-UPDATE index (tid<64 path)

    // ---- weights: 16 ulonglong2 = 64 floats (32 regs) ----
    ulonglong2 w2[16];
    #pragma unroll
    for (int q = 0; q < 8; q++)
        w2[q] = *(const ulonglong2*)(Whh + (size_t)g * Hd + kloc + 4 * q);
    #pragma unroll
    for (int q = 0; q < 8; q++)
        w2[8 + q] = *(const ulonglong2*)(Whh + (size_t)g * Hd + krem + 4 * q);

    uint32_t mb0 = smem_u32(&mbar[0]);
    uint32_t mb1 = smem_u32(&mbar[1]);
    if (tid == 0) {
        mbar_init(mb0, 1); mbar_init(mb1, 1);
        mbar_expect_tx(mb0, 256); mbar_expect_tx(mb1, 256);
    }
    const uint32_t peer = rank ^ 1;
    // remote addresses for the UPDATE path (uidx-based)
    const uint32_t r_h0  = mapa32(smem_u32(&h_s[0][uidx]), peer);
    const uint32_t r_h1  = mapa32(smem_u32(&h_s[1][uidx]), peer);
    const uint32_t r_mb0 = mapa32(mb0, peer);
    const uint32_t r_mb1 = mapa32(mb1, peer);

    float vg = 0.f, ug = 0.f;
    if (LAYER == 0) {
        vg = g_v0[g]; ug = g_u0[g];
        for (int i = tid; i < Tlen; i += 512) xrow[i] = xin[(size_t)b * Tlen + i];
    }
    if (tid < Hd) h_s[0][tid] = 0.f;
    __syncthreads();
    asm volatile("barrier.cluster.arrive.aligned;" ::: "memory");
    asm volatile("barrier.cluster.wait.aligned;" ::: "memory");

    float cst = 0.f, sum = 0.f, mx = -INFINITY, last = 0.f;
    const int len = lengths[b];
    uint32_t ph0 = 0, ph1 = 0;

    float zn = 0.f;
    if (LAYER == 1) zn = g_G1[(size_t)b * G4 + g];   // prefetch t=0 (both pair lanes)

    for (int t = 0; t < Tlen; t++) {
        const int p  = t & 1;
        const int pn = p ^ 1;

        float a_in;
        if (LAYER == 0) {
            a_in = fmaf(xrow[t], vg, ug);
        } else {
            a_in = zn;
            if (t + 1 < Tlen) zn = g_G1[((size_t)(t + 1) * Bsz + b) * G4 + g];
        }

        const ulonglong2* hL = (const ulonglong2*)(&h_s[p][kloc]);
        const ulonglong2* hR = (const ulonglong2*)(&h_s[p][krem]);

        // ---- local k-quarter (peer h still in flight) ----
        unsigned long long acc0 = 0ULL, acc1 = 0ULL;
        #pragma unroll
        for (int q = 0; q < 8; q++) {
            ulonglong2 hv = hL[q];
            fma2(acc0, hv.x, w2[q].x);
            fma2(acc1, hv.y, w2[q].y);
        }
        // ---- wait for peer's 64 h values, then remote k-quarter ----
        if (t > 0) {
            if (p == 0) { mbar_wait(mb0, ph0); ph0 ^= 1; }
            else        { mbar_wait(mb1, ph1); ph1 ^= 1; }
            if (tid == 0) mbar_expect_tx(p ? mb1 : mb0, 256);
        }
        #pragma unroll
        for (int q = 0; q < 8; q++) {
            ulonglong2 hv = hR[q];
            fma2(acc0, hv.x, w2[8 + q].x);
            fma2(acc1, hv.y, w2[8 + q].y);
        }
        float2 u0 = upk2(acc0), u1 = upk2(acc1);
        float half = (u0.x + u0.y) + (u1.x + u1.y);
        float other = __shfl_xor_sync(0xffffffffu, half, 1);
        float lo = kh ? other : half;
        float hi = kh ? half  : other;
        float A = a_in + (lo + hi);          // identical order in both lanes

        float av = (type == 2) ? tanhfast(A) : sigf(A);
        act_s[gi] = av;                      // both lanes write identical value
        __syncthreads();

        if (tid < 64) {
            float iv = act_s[tid],       fv = act_s[64 + tid];
            float gv = act_s[128 + tid], ov = act_s[192 + tid];
            cst = fmaf(fv, cst, iv * gv);
            float h = ov * tanhfast(cst);
            st_async_remote(pn ? r_h1 : r_h0, h, pn ? r_mb1 : r_mb0);
            h_s[pn][uidx] = h;
            if (LAYER == 0) {
                g_H1[((size_t)t * Bsz + b) * Hd + uidx] = h;
            } else {
                if (t < len) { sum += h; mx = fmaxf(mx, h); }
                if (t == len - 1) last = h;
            }
        }
        __syncthreads();
    }

    if (LAYER == 1 && tid < 64) {
        g_pool[b * 384 + uidx]            = sum / (float)len;
        g_pool[b * 384 + Hd + uidx]       = mx;
        g_pool[b * 384 + 2 * Hd + uidx]   = last;
    }
    asm volatile("barrier.cluster.arrive.aligned;" ::: "memory");
    asm volatile("barrier.cluster.wait.aligned;" ::: "memory");
}

// ---------------- TF32 tensor-core GEMM (R11, unchanged): G1 = H1 @ Wih1^T + b1 ----
#define AS_STRIDE 36
#define BS_STRIDE 132
__global__ __launch_bounds__(256)
void gemm_g1_kernel(const float* __restrict__ Wih1, const float* __restrict__ b1) {
    __shared__ uint32_t As[128 * AS_STRIDE];
    __shared__ uint32_t Bs[32 * BS_STRIDE];

    const int m0 = blockIdx.x * 128;
    const int n0 = blockIdx.y * 128;
    const int tid = threadIdx.x;
    const int wid = tid >> 5;
    const int lane = tid & 31;
    const int m_off = (wid & 3) * 32;
    const int n_off = (wid >> 2) * 64;
    const int lr = lane >> 2;
    const int lc = lane & 3;

    float acc[2][8][4];
    #pragma unroll
    for (int mt = 0; mt < 2; mt++)
        #pragma unroll
        for (int nt = 0; nt < 8; nt++)
            #pragma unroll
            for (int i = 0; i < 4; i++) acc[mt][nt][i] = 0.f;

    for (int k0 = 0; k0 < 128; k0 += 32) {
        {
            int r = tid >> 1, cs = (tid & 1) * 16;
            const float* src = g_H1 + (size_t)(m0 + r) * 128 + k0 + cs;
            #pragma unroll
            for (int i = 0; i < 4; i++) {
                float4 v = *(const float4*)(src + 4 * i);
                uint4 tv = make_uint4(f2tf(v.x), f2tf(v.y), f2tf(v.z), f2tf(v.w));
                *(uint4*)&As[r * AS_STRIDE + cs + 4 * i] = tv;
            }
        }
        {
            int n = tid >> 1, ks = (tid & 1) * 16;
            const float* src = Wih1 + (size_t)(n0 + n) * 128 + k0 + ks;
            #pragma unroll
            for (int i = 0; i < 4; i++) {
                float4 v = *(const float4*)(src + 4 * i);
                Bs[(ks + 4 * i + 0) * BS_STRIDE + n] = f2tf(v.x);
                Bs[(ks + 4 * i + 1) * BS_STRIDE + n] = f2tf(v.y);
                Bs[(ks + 4 * i + 2) * BS_STRIDE + n] = f2tf(v.z);
                Bs[(ks + 4 * i + 3) * BS_STRIDE + n] = f2tf(v.w);
            }
        }
        __syncthreads();
        #pragma unroll
        for (int ks = 0; ks < 4; ks++) {
            const int kk = ks * 8;
            uint32_t af[2][4];
            #pragma unroll
            for (int mt = 0; mt < 2; mt++) {
                int row = m_off + mt * 16 + lr;
                af[mt][0] = As[row * AS_STRIDE + kk + lc];
                af[mt][1] = As[(row + 8) * AS_STRIDE + kk + lc];
                af[mt][2] = As[row * AS_STRIDE + kk + lc + 4];
                af[mt][3] = As[(row + 8) * AS_STRIDE + kk + lc + 4];
            }
            #pragma unroll
            for (int nt = 0; nt < 8; nt++) {
                int col = n_off + nt * 8 + lr;
                uint32_t bf[2];
                bf[0] = Bs[(kk + lc) * BS_STRIDE + col];
                bf[1] = Bs[(kk + lc + 4) * BS_STRIDE + col];
                mma_tf32(acc[0][nt], af[0], bf);
                mma_tf32(acc[1][nt], af[1], bf);
            }
        }
        __syncthreads();
    }
    #pragma unroll
    for (int mt = 0; mt < 2; mt++) {
        #pragma unroll
        for (int nt = 0; nt < 8; nt++) {
            int row = m0 + m_off + mt * 16 + lr;
            int col = n0 + n_off + nt * 8 + 2 * lc;
            float bz0 = b1[col], bz1 = b1[col + 1];
            float2 v0 = make_float2(acc[mt][nt][0] + bz0, acc[mt][nt][1] + bz1);
            float2 v1 = make_float2(acc[mt][nt][2] + bz0, acc[mt][nt][3] + bz1);
            *(float2*)(g_G1 + (size_t)row * G4 + col)       = v0;
            *(float2*)(g_G1 + (size_t)(row + 8) * G4 + col) = v1;
        }
    }
}

// ---------------- final linear ----------------
__global__ __launch_bounds__(256)
void final_kernel(const float* __restrict__ lw, const float* __restrict__ lb,
                  float* __restrict__ out) {
    const int b = blockIdx.x;
    const int wid = threadIdx.x >> 5;
    const int lane = threadIdx.x & 31;
    if (wid >= Cout) return;
    float s = 0.f;
    const float* p = g_pool + b * 384;
    const float* wv = lw + wid * 384;
    #pragma unroll
    for (int j = lane; j < 384; j += 32) s = fmaf(p[j], wv[j], s);
    #pragma unroll
    for (int o = 16; o > 0; o >>= 1) s += __shfl_xor_sync(0xffffffff, s, o);
    if (lane == 0) out[b * Cout + wid] = s + lb[wid];
}

// ---------------- launch ----------------
extern "C" void kernel_launch(void* const* d_in, const int* in_sizes, int n_in,
                              void* d_out, int out_size) {
    const float* x    = (const float*)d_in[0];
    const int*   lens = (const int*)  d_in[1];
    const float* ffw  = (const float*)d_in[2];
    const float* ffb  = (const float*)d_in[3];
    const float* Wih0 = (const float*)d_in[4];
    const float* Whh0 = (const float*)d_in[5];
    const float* b0   = (const float*)d_in[6];
    const float* Wih1 = (const float*)d_in[7];
    const float* Whh1 = (const float*)d_in[8];
    const float* b1   = (const float*)d_in[9];
    const float* lw   = (const float*)d_in[10];
    const float* lb   = (const float*)d_in[11];
    float* out = (float*)d_out;

    prep_kernel<<<8, 64>>>(Wih0, ffw, ffb, b0);
    lstm_kernel<0><<<2 * Bsz, 512>>>(Whh0, x, lens);
    dim3 ggrid((Tlen * Bsz) / 128, G4 / 128);
    gemm_g1_kernel<<<ggrid, 256>>>(Wih1, b1);
    lstm_kernel<1><<<2 * Bsz, 512>>>(Whh1, x, lens);
    final_kernel<<<Bsz, 256>>>(lw, lb, out);
}

// round 17
// speedup vs baseline: 2.7221x; 1.3176x over previous
#include <cuda_runtime.h>
#include <math.h>
#include <stdint.h>

#define Bsz  64
#define Tlen 2048
#define Hd   128
#define G4   512
#define Cout 7
#define NWORK 16                   // worker CTAs inside fused kernel A
#define NCHUNK 32                  // 2048 / 64
#define NTILES 4096                // 32 chunks * 128 tiles

// ---------------- device scratch ----------------
__device__ float g_v0[G4];
__device__ float g_u0[G4];
__device__ float g_H1[(size_t)Tlen * Bsz * Hd];
__device__ float g_G1[(size_t)Tlen * Bsz * G4];
__device__ float g_pool[Bsz * 3 * Hd];
__device__ int   g_chunkdone[NCHUNK];
__device__ int   g_tilectr;
__device__ int   g_lstm0_fin;

__device__ __forceinline__ float sigf(float x)  { return 1.0f / (1.0f + __expf(-x)); }
__device__ __forceinline__ float tanhfast(float x) {
    return fmaf(-2.0f, 1.0f / (__expf(2.0f * x) + 1.0f), 1.0f);
}

// ---- packed f32x2 ----
__device__ __forceinline__ void fma2(unsigned long long& d, unsigned long long a, unsigned long long b) {
    asm("fma.rn.f32x2 %0, %1, %2, %0;" : "+l"(d) : "l"(a), "l"(b));
}
__device__ __forceinline__ float2 upk2(unsigned long long v) {
    float2 r; asm("mov.b64 {%0, %1}, %2;" : "=f"(r.x), "=f"(r.y) : "l"(v)); return r;
}

// ---- tf32 ----
__device__ __forceinline__ uint32_t f2tf(float f) {
    uint32_t r; asm("cvt.rna.tf32.f32 %0, %1;" : "=r"(r) : "f"(f)); return r;
}
__device__ __forceinline__ void mma_tf32(float* c, const uint32_t* a, const uint32_t* b) {
    asm("mma.sync.aligned.m16n8k8.row.col.f32.tf32.tf32.f32 "
        "{%0,%1,%2,%3}, {%4,%5,%6,%7}, {%8,%9}, {%0,%1,%2,%3};"
        : "+f"(c[0]), "+f"(c[1]), "+f"(c[2]), "+f"(c[3])
        : "r"(a[0]), "r"(a[1]), "r"(a[2]), "r"(a[3]), "r"(b[0]), "r"(b[1]));
}

__device__ __forceinline__ uint32_t smem_u32(const void* p) {
    uint32_t a;
    asm("{ .reg .u64 t; cvta.to.shared.u64 t, %1; cvt.u32.u64 %0, t; }" : "=r"(a) : "l"(p));
    return a;
}
__device__ __forceinline__ uint32_t mapa32(uint32_t a, uint32_t rank) {
    uint32_t d;
    asm("mapa.shared::cluster.u32 %0, %1, %2;" : "=r"(d) : "r"(a), "r"(rank));
    return d;
}
__device__ __forceinline__ void st_async_remote(uint32_t raddr, float v, uint32_t rmbar) {
    asm volatile("st.async.shared::cluster.mbarrier::complete_tx::bytes.b32 [%0], %1, [%2];"
                 :: "r"(raddr), "r"(__float_as_uint(v)), "r"(rmbar) : "memory");
}
__device__ __forceinline__ void mbar_init(uint32_t mbar, uint32_t cnt) {
    asm volatile("mbarrier.init.shared.b64 [%0], %1;" :: "r"(mbar), "r"(cnt) : "memory");
}
__device__ __forceinline__ void mbar_expect_tx(uint32_t mbar, uint32_t bytes) {
    asm volatile("mbarrier.arrive.expect_tx.shared.b64 _, [%0], %1;" :: "r"(mbar), "r"(bytes) : "memory");
}
__device__ __forceinline__ void mbar_wait(uint32_t mbar, uint32_t parity) {
    uint32_t done;
    asm volatile(
        "{\n\t.reg .pred p;\n\t"
        "mbarrier.try_wait.parity.acquire.cluster.shared::cta.b64 p, [%1], %2;\n\t"
        "selp.b32 %0, 1, 0, p;\n\t}"
        : "=r"(done) : "r"(mbar), "r"(parity) : "memory");
    if (!done) {
        asm volatile(
            "{\n\t.reg .pred P1;\n\t"
            "WL_%=:\n\t"
            "mbarrier.try_wait.parity.acquire.cluster.shared::cta.b64 P1, [%0], %1, 0x989680;\n\t"
            "@P1 bra.uni WD_%=;\n\t"
            "bra.uni WL_%=;\n\t"
            "WD_%=:\n\t}"
            :: "r"(mbar), "r"(parity) : "memory");
    }
}
__device__ __forceinline__ int ld_acq(const int* p) {
    int v;
    asm volatile("ld.global.acquire.gpu.b32 %0, [%1];" : "=r"(v) : "l"(p));
    return v;
}

// ---------------- prep (resets counters each replay) ----------------
__global__ void prep_kernel(const float* __restrict__ Wih0, const float* __restrict__ ffw,
                            const float* __restrict__ ffb,  const float* __restrict__ b0) {
    if (blockIdx.x == 0) {
        if (threadIdx.x < NCHUNK) g_chunkdone[threadIdx.x] = 0;
        if (threadIdx.x == 0) { g_tilectr = 0; g_lstm0_fin = 0; }
    }
    int g = blockIdx.x * 64 + threadIdx.x;
    float v = 0.f, u = 0.f;
    #pragma unroll 8
    for (int k = 0; k < Hd; k++) {
        float w = Wih0[g * Hd + k];
        v = fmaf(w, ffw[k], v);
        u = fmaf(w, ffb[k], u);
    }
    g_v0[g] = v;
    g_u0[g] = u + b0[g];
}

// ---------------- TF32 tile: G1[m0..m0+128)[n0..n0+128) = H1 @ Wih1^T + b1 ----------------
#define AS_STRIDE 36
#define BS_STRIDE 132
__device__ void gemm_tile(uint32_t* As, uint32_t* Bs,
                          const float* __restrict__ Wih1, const float* __restrict__ b1,
                          int m0, int n0, int tid) {
    const int wid = tid >> 5;
    const int lane = tid & 31;
    const int m_off = (wid & 3) * 32;
    const int n_off = (wid >> 2) * 64;
    const int lr = lane >> 2;
    const int lc = lane & 3;

    float acc[2][8][4];
    #pragma unroll
    for (int mt = 0; mt < 2; mt++)
        #pragma unroll
        for (int nt = 0; nt < 8; nt++)
            #pragma unroll
            for (int i = 0; i < 4; i++) acc[mt][nt][i] = 0.f;

    for (int k0 = 0; k0 < 128; k0 += 32) {
        {
            int r = tid >> 1, cs = (tid & 1) * 16;
            const float* src = g_H1 + (size_t)(m0 + r) * 128 + k0 + cs;
            #pragma unroll
            for (int i = 0; i < 4; i++) {
                float4 v = *(const float4*)(src + 4 * i);
                uint4 tv = make_uint4(f2tf(v.x), f2tf(v.y), f2tf(v.z), f2tf(v.w));
                *(uint4*)&As[r * AS_STRIDE + cs + 4 * i] = tv;
            }
        }
        {
            int n = tid >> 1, ks = (tid & 1) * 16;
            const float* src = Wih1 + (size_t)(n0 + n) * 128 + k0 + ks;
            #pragma unroll
            for (int i = 0; i < 4; i++) {
                float4 v = *(const float4*)(src + 4 * i);
                Bs[(ks + 4 * i + 0) * BS_STRIDE + n] = f2tf(v.x);
                Bs[(ks + 4 * i + 1) * BS_STRIDE + n] = f2tf(v.y);
                Bs[(ks + 4 * i + 2) * BS_STRIDE + n] = f2tf(v.z);
                Bs[(ks + 4 * i + 3) * BS_STRIDE + n] = f2tf(v.w);
            }
        }
        __syncthreads();
        #pragma unroll
        for (int ks = 0; ks < 4; ks++) {
            const int kk = ks * 8;
            uint32_t af[2][4];
            #pragma unroll
            for (int mt = 0; mt < 2; mt++) {
                int row = m_off + mt * 16 + lr;
                af[mt][0] = As[row * AS_STRIDE + kk + lc];
                af[mt][1] = As[(row + 8) * AS_STRIDE + kk + lc];
                af[mt][2] = As[row * AS_STRIDE + kk + lc + 4];
                af[mt][3] = As[(row + 8) * AS_STRIDE + kk + lc + 4];
            }
            #pragma unroll
            for (int nt = 0; nt < 8; nt++) {
                int col = n_off + nt * 8 + lr;
                uint32_t bf[2];
                bf[0] = Bs[(kk + lc) * BS_STRIDE + col];
                bf[1] = Bs[(kk + lc + 4) * BS_STRIDE + col];
                mma_tf32(acc[0][nt], af[0], bf);
                mma_tf32(acc[1][nt], af[1], bf);
            }
        }
        __syncthreads();
    }
    #pragma unroll
    for (int mt = 0; mt < 2; mt++) {
        #pragma unroll
        for (int nt = 0; nt < 8; nt++) {
            int row = m0 + m_off + mt * 16 + lr;
            int col = n0 + n_off + nt * 8 + 2 * lc;
            float bz0 = b1[col], bz1 = b1[col + 1];
            float2 v0 = make_float2(acc[mt][nt][0] + bz0, acc[mt][nt][1] + bz1);
            float2 v1 = make_float2(acc[mt][nt][2] + bz0, acc[mt][nt][3] + bz1);
            *(float2*)(g_G1 + (size_t)row * G4 + col)       = v0;
            *(float2*)(g_G1 + (size_t)(row + 8) * G4 + col) = v1;
        }
    }
}

// tile index -> (m0, n0); tiles ordered chunk-major so workers pace naturally
__device__ __forceinline__ void tile_coords(int t, int& m0, int& n0, int& c) {
    c = t >> 7;                     // chunk
    int idx = t & 127;
    m0 = (c * 32 + (idx >> 2)) * 128;
    n0 = (idx & 3) * 128;
}

// ---------------- fused kernel A: lstm0 (128 CTAs, R11) + tile workers (16 CTAs) ----------------
__global__ __launch_bounds__(256, 1) __cluster_dims__(2, 1, 1)
void fused_kernel(const float* __restrict__ Whh0,
                  const float* __restrict__ Wih1, const float* __restrict__ b1,
                  const float* __restrict__ xin) {
    extern __shared__ __align__(16) char dynsm[];

    if (blockIdx.x >= 2 * Bsz) {
        // ================= worker role =================
        uint32_t* As = (uint32_t*)dynsm;
        uint32_t* Bs = As + 128 * AS_STRIDE;
        __shared__ int s_t;
        const int tid = threadIdx.x;
        for (;;) {
            if (tid == 0) {
                s_t = (ld_acq(&g_lstm0_fin) >= 2 * Bsz) ? NTILES
                                                        : atomicAdd(&g_tilectr, 1);
            }
            __syncthreads();
            int t = s_t;
            if (t >= NTILES) break;
            int m0, n0, c;
            tile_coords(t, m0, n0, c);
            if (tid == 0) {
                while (ld_acq(&g_chunkdone[c]) < 2 * Bsz) __nanosleep(256);
            }
            __syncthreads();
            gemm_tile(As, Bs, Wih1, b1, m0, n0, tid);
            __syncthreads();
        }
        return;
    }

    // ================= lstm0 role (R11, unchanged except chunk flags) =================
    __shared__ __align__(16) float h_s[2][Hd];
    __shared__ float act_s[256];
    __shared__ float xrow[Tlen];
    __shared__ __align__(8) unsigned long long mbar[2];

    const int tid  = threadIdx.x;
    const int rank = blockIdx.x & 1;
    const int b    = blockIdx.x >> 1;
    const int type = tid >> 6;
    const int hloc = tid & 63;
    const int h_idx = 64 * rank + hloc;
    const int g    = type * 128 + h_idx;
    const int kloc = 64 * rank;
    const int krem = 64 * (1 - rank);

    ulonglong2 w2[32];
    #pragma unroll
    for (int q = 0; q < 16; q++)
        w2[q] = *(const ulonglong2*)(Whh0 + (size_t)g * Hd + kloc + 4 * q);
    #pragma unroll
    for (int q = 0; q < 16; q++)
        w2[16 + q] = *(const ulonglong2*)(Whh0 + (size_t)g * Hd + krem + 4 * q);

    uint32_t mb0 = smem_u32(&mbar[0]);
    uint32_t mb1 = smem_u32(&mbar[1]);
    if (tid == 0) {
        mbar_init(mb0, 1); mbar_init(mb1, 1);
        mbar_expect_tx(mb0, 256); mbar_expect_tx(mb1, 256);
    }
    const uint32_t peer = rank ^ 1;
    const uint32_t r_h0  = mapa32(smem_u32(&h_s[0][h_idx]), peer);
    const uint32_t r_h1  = mapa32(smem_u32(&h_s[1][h_idx]), peer);
    const uint32_t r_mb0 = mapa32(mb0, peer);
    const uint32_t r_mb1 = mapa32(mb1, peer);

    const float vg = g_v0[g], ug = g_u0[g];
    for (int i = tid; i < Tlen; i += 256) xrow[i] = xin[(size_t)b * Tlen + i];
    if (tid < Hd) h_s[0][tid] = 0.f;
    __syncthreads();
    asm volatile("barrier.cluster.arrive.aligned;" ::: "memory");
    asm volatile("barrier.cluster.wait.aligned;" ::: "memory");

    float cst = 0.f;
    uint32_t ph0 = 0, ph1 = 0;

    for (int t = 0; t < Tlen; t++) {
        const int p  = t & 1;
        const int pn = p ^ 1;

        float a_in = fmaf(xrow[t], vg, ug);

        const ulonglong2* hp = (const ulonglong2*)h_s[p];
        const ulonglong2* hL = hp + (kloc >> 2);
        const ulonglong2* hR = hp + (krem >> 2);

        unsigned long long acc0 = 0ULL, acc1 = 0ULL;
        #pragma unroll
        for (int q = 0; q < 16; q++) {
            ulonglong2 hv = hL[q];
            fma2(acc0, hv.x, w2[q].x);
            fma2(acc1, hv.y, w2[q].y);
        }
        if (t > 0) {
            if (p == 0) { mbar_wait(mb0, ph0); ph0 ^= 1; }
            else        { mbar_wait(mb1, ph1); ph1 ^= 1; }
            if (tid == 0) mbar_expect_tx(p ? mb1 : mb0, 256);
        }
        #pragma unroll
        for (int q = 0; q < 16; q++) {
            ulonglong2 hv = hR[q];
            fma2(acc0, hv.x, w2[16 + q].x);
            fma2(acc1, hv.y, w2[16 + q].y);
        }
        float2 u0 = upk2(acc0), u1 = upk2(acc1);
        float A = a_in + ((u0.x + u0.y) + (u1.x + u1.y));

        float av = (type == 2) ? tanhfast(A) : sigf(A);
        act_s[tid] = av;
        __syncthreads();

        if (tid < 64) {
            float iv = act_s[tid],       fv = act_s[64 + tid];
            float gv = act_s[128 + tid], ov = act_s[192 + tid];
            cst = fmaf(fv, cst, iv * gv);
            float h = ov * tanhfast(cst);
            st_async_remote(pn ? r_h1 : r_h0, h, pn ? r_mb1 : r_mb0);
            h_s[pn][h_idx] = h;
            g_H1[((size_t)t * Bsz + b) * Hd + h_idx] = h;
        }
        __syncthreads();

        if ((t & 63) == 63 && tid == 0) {
            __threadfence();
            atomicAdd(&g_chunkdone[t >> 6], 1);
        }
    }
    if (tid == 0) { __threadfence(); atomicAdd(&g_lstm0_fin, 1); }

    asm volatile("barrier.cluster.arrive.aligned;" ::: "memory");
    asm volatile("barrier.cluster.wait.aligned;" ::: "memory");
}

// ---------------- kernel B: drain remaining tiles at full chip ----------------
__global__ __launch_bounds__(256)
void gemm_drain_kernel(const float* __restrict__ Wih1, const float* __restrict__ b1) {
    extern __shared__ __align__(16) char dynsm[];
    uint32_t* As = (uint32_t*)dynsm;
    uint32_t* Bs = As + 128 * AS_STRIDE;
    __shared__ int s_t;
    const int tid = threadIdx.x;
    for (;;) {
        if (tid == 0) s_t = atomicAdd(&g_tilectr, 1);
        __syncthreads();
        int t = s_t;
        if (t >= NTILES) break;
        int m0, n0, c;
        tile_coords(t, m0, n0, c);
        gemm_tile(As, Bs, Wih1, b1, m0, n0, tid);
        __syncthreads();
    }
}

// ---------------- lstm1 (R11, unchanged) ----------------
__global__ __launch_bounds__(256, 1) __cluster_dims__(2, 1, 1)
void lstm1_kernel(const float* __restrict__ Whh,
                  const int*   __restrict__ lengths) {
    __shared__ __align__(16) float h_s[2][Hd];
    __shared__ float act_s[256];
    __shared__ __align__(8) unsigned long long mbar[2];

    const int tid  = threadIdx.x;
    const int rank = blockIdx.x & 1;
    const int b    = blockIdx.x >> 1;
    const int type = tid >> 6;
    const int hloc = tid & 63;
    const int h_idx = 64 * rank + hloc;
    const int g    = type * 128 + h_idx;
    const int kloc = 64 * rank;
    const int krem = 64 * (1 - rank);

    ulonglong2 w2[32];
    #pragma unroll
    for (int q = 0; q < 16; q++)
        w2[q] = *(const ulonglong2*)(Whh + (size_t)g * Hd + kloc + 4 * q);
    #pragma unroll
    for (int q = 0; q < 16; q++)
        w2[16 + q] = *(const ulonglong2*)(Whh + (size_t)g * Hd + krem + 4 * q);

    uint32_t mb0 = smem_u32(&mbar[0]);
    uint32_t mb1 = smem_u32(&mbar[1]);
    if (tid == 0) {
        mbar_init(mb0, 1); mbar_init(mb1, 1);
        mbar_expect_tx(mb0, 256); mbar_expect_tx(mb1, 256);
    }
    const uint32_t peer = rank ^ 1;
    const uint32_t r_h0  = mapa32(smem_u32(&h_s[0][h_idx]), peer);
    const uint32_t r_h1  = mapa32(smem_u32(&h_s[1][h_idx]), peer);
    const uint32_t r_mb0 = mapa32(mb0, peer);
    const uint32_t r_mb1 = mapa32(mb1, peer);

    if (tid < Hd) h_s[0][tid] = 0.f;
    __syncthreads();
    asm volatile("barrier.cluster.arrive.aligned;" ::: "memory");
    asm volatile("barrier.cluster.wait.aligned;" ::: "memory");

    float cst = 0.f, sum = 0.f, mx = -INFINITY, last = 0.f;
    const int len = lengths[b];
    uint32_t ph0 = 0, ph1 = 0;

    float zn = g_G1[(size_t)b * G4 + g];

    for (int t = 0; t < Tlen; t++) {
        const int p  = t & 1;
        const int pn = p ^ 1;

        float a_in = zn;
        if (t + 1 < Tlen) zn = g_G1[((size_t)(t + 1) * Bsz + b) * G4 + g];

        const ulonglong2* hp = (const ulonglong2*)h_s[p];
        const ulonglong2* hL = hp + (kloc >> 2);
        const ulonglong2* hR = hp + (krem >> 2);

        unsigned long long acc0 = 0ULL, acc1 = 0ULL;
        #pragma unroll
        for (int q = 0; q < 16; q++) {
            ulonglong2 hv = hL[q];
            fma2(acc0, hv.x, w2[q].x);
            fma2(acc1, hv.y, w2[q].y);
        }
        if (t > 0) {
            if (p == 0) { mbar_wait(mb0, ph0); ph0 ^= 1; }
            else        { mbar_wait(mb1, ph1); ph1 ^= 1; }
            if (tid == 0) mbar_expect_tx(p ? mb1 : mb0, 256);
        }
        #pragma unroll
        for (int q = 0; q < 16; q++) {
            ulonglong2 hv = hR[q];
            fma2(acc0, hv.x, w2[16 + q].x);
            fma2(acc1, hv.y, w2[16 + q].y);
        }
        float2 u0 = upk2(acc0), u1 = upk2(acc1);
        float A = a_in + ((u0.x + u0.y) + (u1.x + u1.y));

        float av = (type == 2) ? tanhfast(A) : sigf(A);
        act_s[tid] = av;
        __syncthreads();

        if (tid < 64) {
            float iv = act_s[tid],       fv = act_s[64 + tid];
            float gv = act_s[128 + tid], ov = act_s[192 + tid];
            cst = fmaf(fv, cst, iv * gv);
            float h = ov * tanhfast(cst);
            st_async_remote(pn ? r_h1 : r_h0, h, pn ? r_mb1 : r_mb0);
            h_s[pn][h_idx] = h;
            if (t < len) { sum += h; mx = fmaxf(mx, h); }
            if (t == len - 1) last = h;
        }
        __syncthreads();
    }

    if (tid < 64) {
        g_pool[b * 384 + h_idx]            = sum / (float)len;
        g_pool[b * 384 + Hd + h_idx]       = mx;
        g_pool[b * 384 + 2 * Hd + h_idx]   = last;
    }
    asm volatile("barrier.cluster.arrive.aligned;" ::: "memory");
    asm volatile("barrier.cluster.wait.aligned;" ::: "memory");
}

// ---------------- final linear ----------------
__global__ __launch_bounds__(256)
void final_kernel(const float* __restrict__ lw, const float* __restrict__ lb,
                  float* __restrict__ out) {
    const int b = blockIdx.x;
    const int wid = threadIdx.x >> 5;
    const int lane = threadIdx.x & 31;
    if (wid >= Cout) return;
    float s = 0.f;
    const float* p = g_pool + b * 384;
    const float* wv = lw + wid * 384;
    #pragma unroll
    for (int j = lane; j < 384; j += 32) s = fmaf(p[j], wv[j], s);
    #pragma unroll
    for (int o = 16; o > 0; o >>= 1) s += __shfl_xor_sync(0xffffffff, s, o);
    if (lane == 0) out[b * Cout + wid] = s + lb[wid];
}

// ---------------- launch ----------------
extern "C" void kernel_launch(void* const* d_in, const int* in_sizes, int n_in,
                              void* d_out, int out_size) {
    const float* x    = (const float*)d_in[0];
    const int*   lens = (const int*)  d_in[1];
    const float* ffw  = (const float*)d_in[2];
    const float* ffb  = (const float*)d_in[3];
    const float* Wih0 = (const float*)d_in[4];
    const float* Whh0 = (const float*)d_in[5];
    const float* b0   = (const float*)d_in[6];
    const float* Wih1 = (const float*)d_in[7];
    const float* Whh1 = (const float*)d_in[8];
    const float* b1   = (const float*)d_in[9];
    const float* lw   = (const float*)d_in[10];
    const float* lb   = (const float*)d_in[11];
    float* out = (float*)d_out;

    const int DYN = (128 * AS_STRIDE + 32 * BS_STRIDE) * 4;   // 35.3 KB gemm tiles

    prep_kernel<<<8, 64>>>(Wih0, ffw, ffb, b0);
    fused_kernel<<<2 * Bsz + NWORK, 256, DYN>>>(Whh0, Wih1, b1, x);
    gemm_drain_kernel<<<1024, 256, DYN>>>(Wih1, b1);
    lstm1_kernel<<<2 * Bsz, 256>>>(Whh1, lens);
    final_kernel<<<Bsz, 256>>>(lw, lb, out);
}